// round 4
// baseline (speedup 1.0000x reference)
#include <cuda_runtime.h>
#include <cuda.h>
#include <cuda_fp16.h>
#include <cstdint>

// ===========================================================================
// LinearToeplitz: out[b,o] = sum_i x[b,i] * p[(O-1-o)+i] + bias[o]
// B=8192, I=O=4096.  fp16 mma.sync (HMMA) GEMM, fp32 accumulate.
// sm_100 (non-'a'): no tcgen05 — classic Ampere-style cp.async pipeline.
// ===========================================================================

#define BATCH_SZ 8192
#define IFEAT    4096
#define OFEAT    4096
#define BM 128
#define BN 256
#define BK 64
#define KITERS (IFEAT / BK)       // 64
#define NTHREADS 256
#define STAGES 3
#define STAGE_BYTES 49152u        // A 16KB + B 32KB
#define SMEM_TOTAL (STAGES * STAGE_BYTES)   // 147456

// ------------------------- scratch (static device) -------------------------
__device__ __half g_xh[33554432];   // 64 MB  [8192][4096] fp16 x
__device__ __half g_wh[16777216];   // 32 MB  [4096][4096] fp16 Toeplitz W

// ------------------------- asm helpers -------------------------
__device__ __forceinline__ uint32_t smem_to_u32(const void* p) {
    uint32_t a;
    asm("{ .reg .u64 t; cvta.to.shared.u64 t, %1; cvt.u32.u64 %0, t; }" : "=r"(a) : "l"(p));
    return a;
}
#define CP_ASYNC16(dst, src) \
    asm volatile("cp.async.cg.shared.global [%0], [%1], 16;" :: "r"(dst), "l"(src) : "memory")
#define CP_COMMIT() asm volatile("cp.async.commit_group;" ::: "memory")
#define CP_WAIT1()  asm volatile("cp.async.wait_group 1;" ::: "memory")

#define LDSM4(r0, r1, r2, r3, addr) \
    asm volatile("ldmatrix.sync.aligned.m8n8.x4.shared.b16 {%0,%1,%2,%3}, [%4];" \
        : "=r"(r0), "=r"(r1), "=r"(r2), "=r"(r3) : "r"(addr))

#define MMA16816(d, a, b0, b1) \
    asm volatile("mma.sync.aligned.m16n8k16.row.col.f32.f16.f16.f32 " \
        "{%0,%1,%2,%3},{%4,%5,%6,%7},{%8,%9},{%0,%1,%2,%3};" \
        : "+f"((d)[0]), "+f"((d)[1]), "+f"((d)[2]), "+f"((d)[3]) \
        : "r"((a)[0]), "r"((a)[1]), "r"((a)[2]), "r"((a)[3]), "r"(b0), "r"(b1))

// ------------------------- prep kernels -------------------------
__global__ void prep_x_kernel(const float* __restrict__ x, __half* __restrict__ xh) {
    size_t i = ((size_t)blockIdx.x * blockDim.x + threadIdx.x) * 8;
    float4 v0 = *reinterpret_cast<const float4*>(x + i);
    float4 v1 = *reinterpret_cast<const float4*>(x + i + 4);
    __half2 h[4];
    h[0] = __floats2half2_rn(v0.x, v0.y);
    h[1] = __floats2half2_rn(v0.z, v0.w);
    h[2] = __floats2half2_rn(v1.x, v1.y);
    h[3] = __floats2half2_rn(v1.z, v1.w);
    *reinterpret_cast<uint4*>(xh + i) = *reinterpret_cast<uint4*>(h);
}

// W[o][i] = p[(OFEAT-1-o) + i] : row o is a contiguous slice of p (p is ~32KB,
// L2/L1 resident). Writes fully coalesced 16B.
__global__ void prep_w_kernel(const float* __restrict__ p, __half* __restrict__ wh) {
    int o = blockIdx.x;
    const float* row = p + (OFEAT - 1 - o);
    size_t base = (size_t)o * IFEAT;
    for (int c0 = threadIdx.x * 8; c0 < IFEAT; c0 += blockDim.x * 8) {
        __half2 h[4];
        #pragma unroll
        for (int j = 0; j < 4; ++j)
            h[j] = __floats2half2_rn(__ldg(row + c0 + 2*j), __ldg(row + c0 + 2*j + 1));
        *reinterpret_cast<uint4*>(wh + base + c0) = *reinterpret_cast<uint4*>(h);
    }
}

// ------------------------- GEMM kernel -------------------------
__device__ __forceinline__ void load_stage(uint32_t sb_u32, int slot, int kt, int tid,
                                           const __half* __restrict__ xh,
                                           const __half* __restrict__ wh,
                                           int m0, int n0) {
    const uint32_t sA = sb_u32 + (uint32_t)slot * STAGE_BYTES;
    const uint32_t sB = sA + 16384u;
    const char* gA = reinterpret_cast<const char*>(xh) + ((size_t)m0 * IFEAT + kt * BK) * 2;
    const char* gB = reinterpret_cast<const char*>(wh) + ((size_t)n0 * IFEAT + kt * BK) * 2;
    // A: 128 rows x 128B = 1024 x 16B chunks
    #pragma unroll
    for (int it = 0; it < 4; ++it) {
        int chunk = tid + it * NTHREADS;
        int row = chunk >> 3;
        uint32_t cseg = (chunk & 7) << 4;
        uint32_t dst = sA + (uint32_t)row * 128 + (cseg ^ ((row & 7) << 4));
        CP_ASYNC16(dst, gA + (size_t)row * (IFEAT * 2) + cseg);
    }
    // B: 256 rows x 128B = 2048 x 16B chunks
    #pragma unroll
    for (int it = 0; it < 8; ++it) {
        int chunk = tid + it * NTHREADS;
        int row = chunk >> 3;
        uint32_t cseg = (chunk & 7) << 4;
        uint32_t dst = sB + (uint32_t)row * 128 + (cseg ^ ((row & 7) << 4));
        CP_ASYNC16(dst, gB + (size_t)row * (IFEAT * 2) + cseg);
    }
}

__global__ void __launch_bounds__(NTHREADS, 1) toep_gemm_kernel(
    const __half* __restrict__ xh,
    const __half* __restrict__ wh,
    const float* __restrict__ bias,
    float* __restrict__ out)
{
    extern __shared__ __align__(1024) char smem[];
    const uint32_t sb = smem_to_u32(smem);
    const int tid  = threadIdx.x;
    const int wid  = tid >> 5;
    const int lane = tid & 31;

    const int m0 = blockIdx.y * BM;
    const int n0 = blockIdx.x * BN;

    const int warp_m = wid & 1;    // 2 warps over M (64 rows each)
    const int warp_n = wid >> 1;   // 4 warps over N (64 cols each)

    // ldmatrix per-thread addressing
    const int aRow = warp_m * 64 + (lane & 15);
    const uint32_t aXor = (uint32_t)(aRow & 7) << 4;
    const uint32_t aCol = (uint32_t)(lane >> 4) << 4;       // 0 or 16
    const int bRow = warp_n * 64 + (lane & 7) + ((lane & 16) >> 1);
    const uint32_t bXor = (uint32_t)(bRow & 7) << 4;
    const uint32_t bCol = (uint32_t)(lane & 8) << 1;        // 0 or 16

    float acc[4][8][4];
    #pragma unroll
    for (int mi = 0; mi < 4; ++mi)
        #pragma unroll
        for (int t = 0; t < 8; ++t)
            #pragma unroll
            for (int c = 0; c < 4; ++c) acc[mi][t][c] = 0.0f;

    // prologue: 2 stages in flight
    load_stage(sb, 0, 0, tid, xh, wh, m0, n0); CP_COMMIT();
    load_stage(sb, 1, 1, tid, xh, wh, m0, n0); CP_COMMIT();

    for (int kt = 0; kt < KITERS; ++kt) {
        CP_WAIT1();
        __syncthreads();

        // issue next stage (slot kt+2 mod 3) while computing current
        if (kt + 2 < KITERS)
            load_stage(sb, (kt + 2) % STAGES, kt + 2, tid, xh, wh, m0, n0);
        CP_COMMIT();

        const uint32_t sA = sb + (uint32_t)(kt % STAGES) * STAGE_BYTES;
        const uint32_t sB = sA + 16384u;
        #pragma unroll
        for (int kk = 0; kk < 4; ++kk) {
            const uint32_t kb = (uint32_t)kk * 32;
            uint32_t a[4][4], b[4][4];
            #pragma unroll
            for (int mi = 0; mi < 4; ++mi) {
                uint32_t ad = sA + (uint32_t)(aRow + mi * 16) * 128 + ((kb + aCol) ^ aXor);
                LDSM4(a[mi][0], a[mi][1], a[mi][2], a[mi][3], ad);
            }
            #pragma unroll
            for (int nj = 0; nj < 4; ++nj) {
                uint32_t bd = sB + (uint32_t)(bRow + nj * 16) * 128 + ((kb + bCol) ^ bXor);
                LDSM4(b[nj][0], b[nj][1], b[nj][2], b[nj][3], bd);
            }
            #pragma unroll
            for (int mi = 0; mi < 4; ++mi)
                #pragma unroll
                for (int nj = 0; nj < 4; ++nj) {
                    MMA16816(acc[mi][2 * nj],     a[mi], b[nj][0], b[nj][1]);
                    MMA16816(acc[mi][2 * nj + 1], a[mi], b[nj][2], b[nj][3]);
                }
        }
        __syncthreads();
    }

    // ---------------- epilogue: direct global stores + bias ----------------
    const int cr = lane >> 2;
    const int cc = (lane & 3) * 2;
    const int gn = n0 + warp_n * 64 + cc;

    float2 bb[8];
    #pragma unroll
    for (int t = 0; t < 8; ++t)
        bb[t] = *reinterpret_cast<const float2*>(bias + gn + t * 8);

    #pragma unroll
    for (int mi = 0; mi < 4; ++mi) {
        size_t gm = (size_t)(m0 + warp_m * 64 + mi * 16 + cr);
        float* p0 = out + gm * OFEAT + gn;
        float* p1 = p0 + (size_t)8 * OFEAT;
        #pragma unroll
        for (int t = 0; t < 8; ++t) {
            float2 v0 = make_float2(acc[mi][t][0] + bb[t].x, acc[mi][t][1] + bb[t].y);
            float2 v1 = make_float2(acc[mi][t][2] + bb[t].x, acc[mi][t][3] + bb[t].y);
            *reinterpret_cast<float2*>(p0 + t * 8) = v0;
            *reinterpret_cast<float2*>(p1 + t * 8) = v1;
        }
    }
}

// ------------------------- host launch -------------------------
extern "C" void kernel_launch(void* const* d_in, const int* in_sizes, int n_in,
                              void* d_out, int out_size) {
    const float* x    = (const float*)d_in[0];
    const float* p    = (const float*)d_in[1];
    const float* bias = (const float*)d_in[2];
    float* out        = (float*)d_out;
    (void)in_sizes; (void)n_in; (void)out_size;

    void *pxh = nullptr, *pwh = nullptr;
    cudaGetSymbolAddress(&pxh, g_xh);
    cudaGetSymbolAddress(&pwh, g_wh);

    cudaFuncSetAttribute(toep_gemm_kernel,
                         cudaFuncAttributeMaxDynamicSharedMemorySize, SMEM_TOTAL);

    // prep: x -> fp16, Toeplitz W -> fp16
    prep_x_kernel<<<BATCH_SZ * IFEAT / (256 * 8), 256>>>(x, (__half*)pxh);
    prep_w_kernel<<<OFEAT, 256>>>(p, (__half*)pwh);

    dim3 grid(OFEAT / BN, BATCH_SZ / BM);   // (16, 64)
    toep_gemm_kernel<<<grid, NTHREADS, SMEM_TOTAL>>>(
        (const __half*)pxh, (const __half*)pwh, bias, out);
}